// round 12
// baseline (speedup 1.0000x reference)
#include <cuda_runtime.h>
#include <cuda_bf16.h>
#include <cstdint>

#define NN 100000
#define EE 1600000
#define GG 2000
#define BN_EPS 1e-5f
#define NB 391   // ceil(NN/256)

// ---------------- scratch (static device globals; no runtime alloc) ----------------
__device__ __align__(16) float d_cat[NN * 256];   // cols [0:128)=s_raw=A@act, cols [128:256)=act (raw)
__device__ __align__(16) float d_act[NN * 256];   // layer-6 raw output (pre-BN), for pooling
__device__ int   d_flag;
__device__ int   d_row[EE];
__device__ int   d_colv[EE];
__device__ int   d_deg[NN];
__device__ float d_dinv[NN];
__device__ int   d_off[NN + 1];
__device__ int   d_cur[NN];
__device__ int   d_bsum[512];
__device__ __align__(16) int2 d_edge[EE];         // {src, nrm-as-int}
__device__ float d_wsum[NN];
__device__ int   d_goff[GG + 1];
__device__ __align__(16) float d_Wcat[5 * 256 * 128 + 256 * 256];  // [Wi;Wr] per layer, [256,F] row-major
__device__ __align__(16) unsigned int d_Bhi[256 * 128];  // B hi: [n][kp] bf16x2, row = 128 uints
__device__ __align__(16) unsigned int d_Blo[256 * 128];  // B lo
__device__ float d_stats[512];
__device__ float d_scl[256];
__device__ float d_shl[256];
__device__ float d_u[256];
__device__ float d_b2[256];

// ---------------- mma.sync helper (sm_80+ portable HMMA) ----------------
__device__ __forceinline__ void mma16816(float* c, const uint32_t* a, uint32_t b0, uint32_t b1) {
    asm volatile(
        "mma.sync.aligned.m16n8k16.row.col.f32.bf16.bf16.f32 "
        "{%0,%1,%2,%3}, {%4,%5,%6,%7}, {%8,%9}, {%0,%1,%2,%3};"
        : "+f"(c[0]), "+f"(c[1]), "+f"(c[2]), "+f"(c[3])
        : "r"(a[0]), "r"(a[1]), "r"(a[2]), "r"(a[3]), "r"(b0), "r"(b1));
}

// ---------------- dtype detection ----------------
__global__ void k_detect(const unsigned int* __restrict__ buf) {
    __shared__ int any;
    if (threadIdx.x == 0) any = 0;
    __syncthreads();
    const int S = 2 * EE / 2048;
    for (int k = threadIdx.x; k < 1024; k += blockDim.x) {
        unsigned int w = buf[2 * (k * S) + 1];
        if (w != 0u) atomicOr(&any, 1);
    }
    __syncthreads();
    if (threadIdx.x == 0) d_flag = (any == 0) ? 1 : 0;
}

__global__ void k_extract_copy(const void* __restrict__ eiv, const float* __restrict__ x) {
    int i = blockIdx.x * blockDim.x + threadIdx.x;
    if (i < NN * 32) {
        int n = i >> 5, c = i & 31;
        ((float4*)d_cat)[n * 64 + 32 + c] = ((const float4*)x)[i];
    }
    if (i < NN) d_deg[i] = 0;
    if (i < EE) {
        int r, c;
        if (d_flag) {
            const long long* p = (const long long*)eiv;
            r = (int)p[i]; c = (int)p[EE + i];
        } else {
            const int* p = (const int*)eiv;
            r = p[i]; c = p[EE + i];
        }
        d_row[i] = r; d_colv[i] = c;
    }
}

__global__ void k_count() {
    int e = blockIdx.x * blockDim.x + threadIdx.x;
    if (e < EE) atomicAdd(&d_deg[d_colv[e]], 1);
}

// ---------------- grid-wide exclusive scan (3 phases) ----------------
__global__ void k_scan1() {
    __shared__ int sh[256];
    int i = blockIdx.x * 256 + threadIdx.x;
    sh[threadIdx.x] = (i < NN) ? d_deg[i] : 0;
    __syncthreads();
#pragma unroll
    for (int o = 128; o > 0; o >>= 1) {
        if (threadIdx.x < o) sh[threadIdx.x] += sh[threadIdx.x + o];
        __syncthreads();
    }
    if (threadIdx.x == 0) d_bsum[blockIdx.x] = sh[0];
}

__global__ void k_scan2() {
    __shared__ int sh[512];
    int t = threadIdx.x;
    int v = (t < NB) ? d_bsum[t] : 0;
    sh[t] = v;
    __syncthreads();
    for (int o = 1; o < 512; o <<= 1) {
        int u = (t >= o) ? sh[t - o] : 0;
        __syncthreads();
        sh[t] += u;
        __syncthreads();
    }
    if (t < NB) d_bsum[t] = sh[t] - v;
}

__global__ void k_scan3() {
    __shared__ int sh[256];
    int i = blockIdx.x * 256 + threadIdx.x;
    int d = (i < NN) ? d_deg[i] : 0;
    sh[threadIdx.x] = d;
    __syncthreads();
    for (int o = 1; o < 256; o <<= 1) {
        int u = (threadIdx.x >= o) ? sh[threadIdx.x - o] : 0;
        __syncthreads();
        sh[threadIdx.x] += u;
        __syncthreads();
    }
    if (i < NN) {
        int run = d_bsum[blockIdx.x] + sh[threadIdx.x] - d;
        d_off[i] = run;
        d_cur[i] = run;
        d_dinv[i] = (d > 0) ? rsqrtf((float)d) : 0.0f;
        if (i == NN - 1) d_off[NN] = EE;
    }
}

__global__ void k_fill() {
    int e = blockIdx.x * blockDim.x + threadIdx.x;
    if (e < EE) {
        int r = d_row[e];
        int c = d_colv[e];
        int p = atomicAdd(&d_cur[c], 1);
        d_edge[p] = make_int2(r, __float_as_int(d_dinv[r] * d_dinv[c]));
    }
}

__global__ void k_wsum() {
    int w = (blockIdx.x * blockDim.x + threadIdx.x) >> 5;
    int lane = threadIdx.x & 31;
    if (w >= NN) return;
    int s0 = d_off[w], s1 = d_off[w + 1];
    float s = 0.f;
    for (int k = s0 + lane; k < s1; k += 32) s += __int_as_float(__ldg(&d_edge[k]).y);
#pragma unroll
    for (int o = 16; o > 0; o >>= 1) s += __shfl_xor_sync(0xffffffffu, s, o);
    if (lane == 0) d_wsum[w] = s;
}

__global__ void k_wcat(const float* __restrict__ Wi, const float* __restrict__ Wr,
                       const float* __restrict__ Wi6, const float* __restrict__ Wr6) {
    int i = blockIdx.x * blockDim.x + threadIdx.x;
    const int L5 = 5 * 256 * 128;
    if (i < L5) {
        int l = i >> 15;
        int rem = i & 32767;
        int k = rem >> 7, f = rem & 127;
        d_Wcat[i] = (k < 128) ? Wi[(l << 14) + (k << 7) + f]
                              : Wr[(l << 14) + ((k - 128) << 7) + f];
    } else if (i < L5 + 65536) {
        int j = i - L5;
        int k = j >> 8, f = j & 255;
        d_Wcat[i] = (k < 128) ? Wi6[(k << 8) + f] : Wr6[((k - 128) << 8) + f];
    }
}

__global__ void k_goff(const void* __restrict__ bv) {
    int n = blockIdx.x * blockDim.x + threadIdx.x;
    if (n >= NN) return;
    int bn, bp;
    if (d_flag) {
        const long long* p = (const long long*)bv;
        bn = (int)p[n]; bp = (n == 0) ? -1 : (int)p[n - 1];
    } else {
        const int* p = (const int*)bv;
        bn = p[n]; bp = (n == 0) ? -1 : p[n - 1];
    }
    for (int id = bp + 1; id <= bn; id++) d_goff[id] = n;
    if (n == NN - 1)
        for (int id = bn + 1; id <= GG; id++) d_goff[id] = NN;
}

// ---------------- BN fold: scl/shl from stats; init u/b2/stats ----------------
__global__ void k_bnfold(const float* __restrict__ gamma, const float* __restrict__ beta,
                         const float* __restrict__ b, int Nn, int ident) {
    int f = threadIdx.x;   // 256
    if (f < 128) {
        float sc, sh;
        if (ident) { sc = 1.f; sh = 0.f; }
        else {
            float mu = d_stats[f] * (1.f / NN);
            float var = d_stats[256 + f] * (1.f / NN) - mu * mu;
            sc = gamma[f] * rsqrtf(var + BN_EPS);
            sh = beta[f] - mu * sc;
        }
        d_scl[f] = sc;
        d_shl[f] = sh;
    }
    d_stats[f] = 0.f;
    d_stats[256 + f] = 0.f;
    if (f < Nn) { d_u[f] = 0.f; d_b2[f] = b[f]; }
}

// fused: blocks [0,Nn) = B scale+split; blocks [Nn,Nn+16) = u/b2 rank-1 accumulation
__global__ void k_prep2(const float* __restrict__ Wi, const float* __restrict__ Wr,
                        int wofs, int Nn) {
    int bx = blockIdx.x;
    if (bx < Nn) {
        int n = bx, k = threadIdx.x;   // 256 k values
        float w = d_scl[k & 127] * d_Wcat[wofs + k * Nn + n];
        __nv_bfloat16 h = __float2bfloat16(w);
        __nv_bfloat16 l = __float2bfloat16(w - __bfloat162float(h));
        ((__nv_bfloat16*)d_Bhi)[n * 256 + k] = h;
        ((__nv_bfloat16*)d_Blo)[n * 256 + k] = l;
    } else {
        int f = threadIdx.x;
        if (f < Nn) {
            int k0 = (bx - Nn) * 8;
            float u = 0.f, bb = 0.f;
#pragma unroll
            for (int k = k0; k < k0 + 8; k++) {
                float sh = d_shl[k];
                u  = fmaf(sh, Wi[k * Nn + f], u);
                bb = fmaf(sh, Wr[k * Nn + f], bb);
            }
            atomicAdd(&d_u[f], u);
            atomicAdd(&d_b2[f], bb);
        }
    }
}

// ---------------- SpMM: warp per node, 4-edge unroll (MLP 4) ----------------
__global__ void k_spmm() {
    int w = (blockIdx.x * blockDim.x + threadIdx.x) >> 5;
    int lane = threadIdx.x & 31;
    if (w >= NN) return;
    int s0 = d_off[w], s1 = d_off[w + 1];
    float4 acc = make_float4(0.f, 0.f, 0.f, 0.f);
    const float4* hb = (const float4*)d_cat;
    int k = s0;
    for (; k + 3 < s1; k += 4) {
        int2 e0 = __ldg(&d_edge[k]);
        int2 e1 = __ldg(&d_edge[k + 1]);
        int2 e2 = __ldg(&d_edge[k + 2]);
        int2 e3 = __ldg(&d_edge[k + 3]);
        float4 v0 = __ldg(&hb[e0.x * 64 + 32 + lane]);
        float4 v1 = __ldg(&hb[e1.x * 64 + 32 + lane]);
        float4 v2 = __ldg(&hb[e2.x * 64 + 32 + lane]);
        float4 v3 = __ldg(&hb[e3.x * 64 + 32 + lane]);
        float w0 = __int_as_float(e0.y), w1 = __int_as_float(e1.y);
        float w2 = __int_as_float(e2.y), w3 = __int_as_float(e3.y);
        acc.x = fmaf(w0, v0.x, acc.x); acc.y = fmaf(w0, v0.y, acc.y);
        acc.z = fmaf(w0, v0.z, acc.z); acc.w = fmaf(w0, v0.w, acc.w);
        acc.x = fmaf(w1, v1.x, acc.x); acc.y = fmaf(w1, v1.y, acc.y);
        acc.z = fmaf(w1, v1.z, acc.z); acc.w = fmaf(w1, v1.w, acc.w);
        acc.x = fmaf(w2, v2.x, acc.x); acc.y = fmaf(w2, v2.y, acc.y);
        acc.z = fmaf(w2, v2.z, acc.z); acc.w = fmaf(w2, v2.w, acc.w);
        acc.x = fmaf(w3, v3.x, acc.x); acc.y = fmaf(w3, v3.y, acc.y);
        acc.z = fmaf(w3, v3.z, acc.z); acc.w = fmaf(w3, v3.w, acc.w);
    }
    for (; k < s1; k++) {
        int2 e = __ldg(&d_edge[k]);
        float wt = __int_as_float(e.y);
        float4 v = __ldg(&hb[e.x * 64 + 32 + lane]);
        acc.x = fmaf(wt, v.x, acc.x); acc.y = fmaf(wt, v.y, acc.y);
        acc.z = fmaf(wt, v.z, acc.z); acc.w = fmaf(wt, v.w, acc.w);
    }
    ((float4*)d_cat)[w * 64 + lane] = acc;
}

// ---------------- HMMA GEMM (mma.sync bf16 hi/lo split) + fused BN stats:
//   D = [s_raw|act] @ Bsplit ; out = ReLU(D + wsum*u + b2); d_stats += colwise sum/sumsq
__global__ void __launch_bounds__(256, 2) k_gemm_mma(int toCat) {
    __shared__ uint32_t sA[2][128][12];   // [hi/lo][row][kp] bf16x2, stride-12 pad
    __shared__ uint32_t sB[2][128][12];
    __shared__ float ssum[128], ssq[128];
    int tid = threadIdx.x;
    int warp = tid >> 5, lane = tid & 31;
    int wm = warp & 3, wn = warp >> 2;        // 4 x 2 warp grid
    int bm = blockIdx.x * 128, bn = blockIdx.y * 128;
    int lr = lane >> 2, lq = lane & 3;

    float acc[2][8][4];
#pragma unroll
    for (int i = 0; i < 2; i++)
#pragma unroll
        for (int j = 0; j < 8; j++)
#pragma unroll
            for (int q = 0; q < 4; q++) acc[i][j][q] = 0.f;

    for (int c = 0; c < 16; c++) {
        // stage A: 128 rows x 16 k (8 kp) fp32 -> bf16 hi/lo pairs
#pragma unroll
        for (int it = 0; it < 4; it++) {
            int idx = it * 256 + tid;
            int row = idx >> 3, j = idx & 7;
            int m = bm + row;
            float2 v = (m < NN) ? *(const float2*)(d_cat + m * 256 + c * 16 + 2 * j)
                                : make_float2(0.f, 0.f);
            uint32_t hp, lp;
            asm("cvt.rn.bf16x2.f32 %0, %1, %2;" : "=r"(hp) : "f"(v.y), "f"(v.x));
            float h0 = __uint_as_float(hp << 16);
            float h1 = __uint_as_float(hp & 0xFFFF0000u);
            asm("cvt.rn.bf16x2.f32 %0, %1, %2;" : "=r"(lp) : "f"(v.y - h1), "f"(v.x - h0));
            sA[0][row][j] = hp;
            sA[1][row][j] = lp;
        }
        // stage B: 128 n x 8 kp from pre-split global
#pragma unroll
        for (int it = 0; it < 4; it++) {
            int idx = it * 256 + tid;
            int n = idx >> 3, j = idx & 7;
            sB[0][n][j] = d_Bhi[(bn + n) * 128 + c * 8 + j];
            sB[1][n][j] = d_Blo[(bn + n) * 128 + c * 8 + j];
        }
        __syncthreads();

        uint32_t ah[2][4], al[2][4];
#pragma unroll
        for (int mt = 0; mt < 2; mt++) {
            int r = wm * 32 + mt * 16 + lr;
            ah[mt][0] = sA[0][r][lq];     ah[mt][1] = sA[0][r + 8][lq];
            ah[mt][2] = sA[0][r][lq + 4]; ah[mt][3] = sA[0][r + 8][lq + 4];
            al[mt][0] = sA[1][r][lq];     al[mt][1] = sA[1][r + 8][lq];
            al[mt][2] = sA[1][r][lq + 4]; al[mt][3] = sA[1][r + 8][lq + 4];
        }
#pragma unroll
        for (int nt = 0; nt < 8; nt++) {
            int n = wn * 64 + nt * 8 + lr;
            uint32_t bh0 = sB[0][n][lq], bh1 = sB[0][n][lq + 4];
            uint32_t bl0 = sB[1][n][lq], bl1 = sB[1][n][lq + 4];
            mma16816(acc[0][nt], ah[0], bh0, bh1);
            mma16816(acc[0][nt], ah[0], bl0, bl1);
            mma16816(acc[0][nt], al[0], bh0, bh1);
            mma16816(acc[1][nt], ah[1], bh0, bh1);
            mma16816(acc[1][nt], ah[1], bl0, bl1);
            mma16816(acc[1][nt], al[1], bh0, bh1);
        }
        __syncthreads();
    }

    // epilogue: fold rank-1 + bias, ReLU, store, accumulate BN stats into smem
    if (tid < 128) { ssum[tid] = 0.f; ssq[tid] = 0.f; }
    int rr[4]; float ws[4]; bool ok[4];
#pragma unroll
    for (int mt = 0; mt < 2; mt++)
#pragma unroll
        for (int half = 0; half < 2; half++) {
            int idx = mt * 2 + half;
            int r = bm + wm * 32 + mt * 16 + lr + half * 8;
            rr[idx] = r; ok[idx] = (r < NN);
            ws[idx] = ok[idx] ? d_wsum[r] : 0.f;
        }
    __syncthreads();
#pragma unroll
    for (int nt = 0; nt < 8; nt++) {
        int lc = wn * 64 + nt * 8 + 2 * lq;   // local col 0..127
        int col = bn + lc;
        float b20 = d_b2[col], b21 = d_b2[col + 1];
        float u0 = d_u[col], u1 = d_u[col + 1];
        float s0 = 0.f, s1 = 0.f, q0 = 0.f, q1 = 0.f;
#pragma unroll
        for (int mt = 0; mt < 2; mt++)
#pragma unroll
            for (int half = 0; half < 2; half++) {
                int idx = mt * 2 + half;
                if (ok[idx]) {
                    float v0 = acc[mt][nt][half * 2 + 0] + b20 + ws[idx] * u0;
                    float v1 = acc[mt][nt][half * 2 + 1] + b21 + ws[idx] * u1;
                    v0 = v0 > 0.f ? v0 : 0.f;
                    v1 = v1 > 0.f ? v1 : 0.f;
                    float2 o = make_float2(v0, v1);
                    if (toCat) *(float2*)&d_cat[rr[idx] * 256 + 128 + col] = o;
                    else       *(float2*)&d_act[rr[idx] * 256 + col] = o;
                    s0 += v0; s1 += v1; q0 += v0 * v0; q1 += v1 * v1;
                }
            }
        atomicAdd(&ssum[lc], s0); atomicAdd(&ssum[lc + 1], s1);
        atomicAdd(&ssq[lc], q0);  atomicAdd(&ssq[lc + 1], q1);
    }
    __syncthreads();
    if (tid < 128) {
        atomicAdd(&d_stats[bn + tid], ssum[tid]);
        atomicAdd(&d_stats[256 + bn + tid], ssq[tid]);
    }
}

// ---------------- final BN coefs for pool ----------------
__global__ void k_mkbn(const float* __restrict__ gamma, const float* __restrict__ beta, int F) {
    int f = threadIdx.x;
    if (f >= F) return;
    float mu = d_stats[f] * (1.f / NN);
    float var = d_stats[256 + f] * (1.f / NN) - mu * mu;
    float sc = gamma[f] * rsqrtf(var + BN_EPS);
    d_scl[f] = sc;
    d_shl[f] = beta[f] - mu * sc;
}

__global__ void k_pool(float* __restrict__ out) {
    int g = blockIdx.x, f = threadIdx.x;
    int n0 = d_goff[g], n1 = d_goff[g + 1];
    float s = 0.f;
    for (int n = n0; n < n1; n++) s += d_act[n * 256 + f];
    out[g * 256 + f] = d_scl[f] * s + (float)(n1 - n0) * d_shl[f];
}

// ---------------- launch ----------------
extern "C" void kernel_launch(void* const* d_in, const int* in_sizes, int n_in,
                              void* d_out, int out_size) {
    const float* x   = (const float*)d_in[0];
    const void*  ei  = d_in[1];
    const void*  bat = d_in[2];
    const float* Wi  = (const float*)d_in[3];
    const float* Wr  = (const float*)d_in[4];
    const float* b   = (const float*)d_in[5];
    const float* g   = (const float*)d_in[6];
    const float* be  = (const float*)d_in[7];
    const float* Wi6 = (const float*)d_in[8];
    const float* Wr6 = (const float*)d_in[9];
    const float* b6  = (const float*)d_in[10];
    const float* g6  = (const float*)d_in[11];
    const float* be6 = (const float*)d_in[12];
    float* out = (float*)d_out;

    k_detect<<<1, 256>>>((const unsigned int*)ei);
    k_extract_copy<<<(NN * 32 + 255) / 256, 256>>>(ei, x);
    k_count<<<(EE + 255) / 256, 256>>>();
    k_scan1<<<NB, 256>>>();
    k_scan2<<<1, 512>>>();
    k_scan3<<<NB, 256>>>();
    k_fill<<<(EE + 255) / 256, 256>>>();
    k_wsum<<<(NN + 7) / 8, 256>>>();
    k_wcat<<<(5 * 32768 + 65536 + 255) / 256, 256>>>(Wi, Wr, Wi6, Wr6);
    k_goff<<<(NN + 255) / 256, 256>>>(bat);

    const int mblocks = (NN + 127) / 128;  // 782
    for (int l = 0; l < 5; l++) {
        k_spmm<<<(NN + 7) / 8, 256>>>();
        k_bnfold<<<1, 256>>>(g + (l - 1) * 128, be + (l - 1) * 128, b + l * 128, 128, l == 0);
        k_prep2<<<128 + 16, 256>>>(Wi + l * 16384, Wr + l * 16384, l * 32768, 128);
        k_gemm_mma<<<dim3(mblocks, 1), 256>>>(1);
    }
    // layer 6 (F_OUT = 256)
    k_spmm<<<(NN + 7) / 8, 256>>>();
    k_bnfold<<<1, 256>>>(g + 4 * 128, be + 4 * 128, b6, 256, 0);
    k_prep2<<<256 + 16, 256>>>(Wi6, Wr6, 5 * 32768, 256);
    k_gemm_mma<<<dim3(mblocks, 2), 256>>>(0);

    k_mkbn<<<1, 256>>>(g6, be6, 256);
    k_pool<<<GG, 256>>>(out);
}